// round 2
// baseline (speedup 1.0000x reference)
#include <cuda_runtime.h>
#include <cstddef>

#define D 128
#define NP 200000
#define NA 150000
#define NI 10000
#define BM 64
#define EPS 1e-5f

// ---------------- scratch (device globals; no allocation allowed) -------------
__device__ float g_P0[(size_t)NP * D];
__device__ float g_A0[(size_t)NA * D];
__device__ float g_P1[(size_t)NP * D];
__device__ float g_A1[(size_t)NA * D];
__device__ float g_I1[(size_t)NI * D];
__device__ float g_AGG[(size_t)NP * D];
__device__ int   g_cnt[5][NP];
__device__ float g_inv[5][NP];
__device__ float g_bnsum[D];
__device__ float g_bnsq[D];

// ---------------- kernels ----------------------------------------------------

__global__ void k_count(const int* __restrict__ dst, int E, int* __restrict__ cnt) {
    int i = blockIdx.x * blockDim.x + threadIdx.x;
    if (i < E) atomicAdd(&cnt[dst[i]], 1);
}

__global__ void k_inv(const int* __restrict__ cnt, float* __restrict__ inv, int n) {
    int i = blockIdx.x * blockDim.x + threadIdx.x;
    if (i < n) inv[i] = 1.0f / (float)max(cnt[i], 1);
}

// One warp per edge; each lane moves one float4 (coalesced 512B read) and does
// 4 scalar atomicAdds into the destination row.
__global__ void k_scatter(const float* __restrict__ x, const int* __restrict__ src,
                          const int* __restrict__ dst, int E, float* __restrict__ agg) {
    int gid  = blockIdx.x * blockDim.x + threadIdx.x;
    int e    = gid >> 5;
    int lane = gid & 31;
    if (e >= E) return;
    int s = src[e], d = dst[e];
    float4 v = ((const float4*)(x + (size_t)s * D))[lane];
    float* a = agg + (size_t)d * D + lane * 4;
    atomicAdd(a + 0, v.x);
    atomicAdd(a + 1, v.y);
    atomicAdd(a + 2, v.z);
    atomicAdd(a + 3, v.w);
}

// out[N,128] (+)= (A1 * inv)[N,128] @ W1[128,128]  (+ A2[N,128] @ W2[128,128]) + bias
// Fused as a [N, K]x[K, 128] GEMM with K = 128 or 256. W fully resident in smem.
// 128 threads, BM=64 rows per block, 8x8 register tile per thread.
__global__ void __launch_bounds__(128)
k_gemm(const float* __restrict__ A1, const float* __restrict__ inv,
       const float* __restrict__ W1,
       const float* __restrict__ A2, const float* __restrict__ W2,
       const float* __restrict__ bias,
       float* __restrict__ out, int N, int accumulate) {
    extern __shared__ float sm[];
    const int K  = A2 ? 256 : 128;
    const int Kq = K >> 2;
    float* sW = sm;            // K * 128
    float* sA = sm + K * D;    // BM * K
    int tid  = threadIdx.x;
    int base = blockIdx.x * BM;

    // load weights: rows [0,128) from W1, [128,256) from W2
    for (int idx = tid; idx < K * 32; idx += 128) {
        int k  = idx >> 5;
        int n4 = idx & 31;
        const float* wsrc = (k < 128) ? (W1 + (size_t)k * D) : (W2 + (size_t)(k - 128) * D);
        ((float4*)(sW + (size_t)k * D))[n4] = ((const float4*)wsrc)[n4];
    }
    // load A tile: first 128 cols = A1 * inv[row], next 128 = A2
    for (int idx = tid; idx < BM * Kq; idx += 128) {
        int r   = idx / Kq;
        int c4  = idx % Kq;
        int row = base + r;
        float4 v = make_float4(0.f, 0.f, 0.f, 0.f);
        if (row < N) {
            if (c4 < 32) {
                v = ((const float4*)(A1 + (size_t)row * D))[c4];
                float s = inv[row];
                v.x *= s; v.y *= s; v.z *= s; v.w *= s;
            } else {
                v = ((const float4*)(A2 + (size_t)row * D))[c4 - 32];
            }
        }
        ((float4*)(sA + (size_t)r * K))[c4] = v;
    }
    __syncthreads();

    int tx = tid & 15;   // 16 col-groups * 8 cols = 128
    int ty = tid >> 4;   // 8 row-groups  * 8 rows = 64
    float acc[8][8];
#pragma unroll
    for (int i = 0; i < 8; i++)
#pragma unroll
        for (int j = 0; j < 8; j++) acc[i][j] = 0.f;

#pragma unroll 4
    for (int k = 0; k < K; k++) {
        float a[8];
#pragma unroll
        for (int i = 0; i < 8; i++) a[i] = sA[(size_t)(ty * 8 + i) * K + k];
        float4 b0 = ((const float4*)(sW + (size_t)k * D))[tx * 2];
        float4 b1 = ((const float4*)(sW + (size_t)k * D))[tx * 2 + 1];
        float b[8] = {b0.x, b0.y, b0.z, b0.w, b1.x, b1.y, b1.z, b1.w};
#pragma unroll
        for (int i = 0; i < 8; i++)
#pragma unroll
            for (int j = 0; j < 8; j++) acc[i][j] = fmaf(a[i], b[j], acc[i][j]);
    }

    float bb[8];
#pragma unroll
    for (int j = 0; j < 8; j++) bb[j] = bias[tx * 8 + j];

#pragma unroll
    for (int i = 0; i < 8; i++) {
        int row = base + ty * 8 + i;
        if (row >= N) continue;
        float* o = out + (size_t)row * D + tx * 8;
        if (accumulate) {
#pragma unroll
            for (int j = 0; j < 8; j++) o[j] += acc[i][j] + bb[j];
        } else {
#pragma unroll
            for (int j = 0; j < 8; j++) o[j] = acc[i][j] + bb[j];
        }
    }
}

// BN over relu(x): pass 1 = per-column sum / sumsq of relu(x)
__global__ void k_bnstats(const float* __restrict__ x, int N) {
    int c = threadIdx.x;  // 128 threads
    float s = 0.f, sq = 0.f;
    for (int r = blockIdx.x; r < N; r += gridDim.x) {
        float v = fmaxf(x[(size_t)r * D + c], 0.f);
        s += v; sq += v * v;
    }
    atomicAdd(&g_bnsum[c], s);
    atomicAdd(&g_bnsq[c], sq);
}

// pass 2: x = (relu(x)-m) * rsqrt(var+eps) * g + b  (in place)
__global__ void k_bnapply(float* __restrict__ x, int N,
                          const float* __restrict__ g, const float* __restrict__ b) {
    int idx = blockIdx.x * blockDim.x + threadIdx.x;
    if (idx >= N * D) return;
    int c = idx & (D - 1);
    float m   = g_bnsum[c] / (float)N;
    float var = g_bnsq[c] / (float)N - m * m;
    float v = fmaxf(x[idx], 0.f);
    x[idx] = (v - m) * rsqrtf(var + EPS) * g[c] + b[c];
}

// ---------------- host orchestration -----------------------------------------

extern "C" void kernel_launch(void* const* d_in, const int* in_sizes, int n_in,
                              void* d_out, int out_size) {
    const float* x_p = (const float*)d_in[0];
    const float* x_a = (const float*)d_in[1];
    const int* e_pp = (const int*)d_in[3];
    const int* e_pa = (const int*)d_in[4];
    const int* e_ap = (const int*)d_in[5];
    const int* e_ai = (const int*)d_in[6];
    const int* e_ia = (const int*)d_in[7];
    const float* Wl  = (const float*)d_in[8];
    const float* bL  = (const float*)d_in[9];
    const float* Wr  = (const float*)d_in[10];
    const float* bng = (const float*)d_in[11];
    const float* bnb = (const float*)d_in[12];

    const int np = in_sizes[0] / D;
    const int na = in_sizes[1] / D;
    const int ni = in_sizes[2] / D;
    const int Epp = in_sizes[3] / 2, Epa = in_sizes[4] / 2, Eap = in_sizes[5] / 2;
    const int Eai = in_sizes[6] / 2, Eia = in_sizes[7] / 2;

    float *P0, *A0, *P1, *A1, *I1, *AGG, *bnsum, *bnsq;
    int   (*cnt)[NP];
    float (*inv)[NP];
    cudaGetSymbolAddress((void**)&P0,  g_P0);
    cudaGetSymbolAddress((void**)&A0,  g_A0);
    cudaGetSymbolAddress((void**)&P1,  g_P1);
    cudaGetSymbolAddress((void**)&A1,  g_A1);
    cudaGetSymbolAddress((void**)&I1,  g_I1);
    cudaGetSymbolAddress((void**)&AGG, g_AGG);
    cudaGetSymbolAddress((void**)&cnt, g_cnt);
    cudaGetSymbolAddress((void**)&inv, g_inv);
    cudaGetSymbolAddress((void**)&bnsum, g_bnsum);
    cudaGetSymbolAddress((void**)&bnsq,  g_bnsq);

    cudaFuncSetAttribute(k_gemm, cudaFuncAttributeMaxDynamicSharedMemorySize, 196608);

    // ---- per-edge-type in-degree counts + reciprocals (deterministic, recomputed) ----
    struct { const int* e; int E; int ndst; } cl[5] = {
        {e_pp, Epp, np}, {e_pa, Epa, na}, {e_ap, Eap, np}, {e_ai, Eai, ni}, {e_ia, Eia, na}};
    for (int t = 0; t < 5; t++) {
        cudaMemsetAsync(cnt[t], 0, (size_t)cl[t].ndst * sizeof(int), 0);
        k_count<<<(cl[t].E + 255) / 256, 256>>>(cl[t].e + cl[t].E, cl[t].E, cnt[t]);
        k_inv<<<(cl[t].ndst + 255) / 256, 256>>>(cnt[t], inv[t], cl[t].ndst);
    }

    auto scatter = [&](const float* x, const int* e, int E, int ndst) {
        cudaMemsetAsync(AGG, 0, (size_t)ndst * D * sizeof(float), 0);
        long long thr = (long long)E * 32;
        k_scatter<<<(unsigned)((thr + 255) / 256), 256>>>(x, e, e + E, E, AGG);
    };
    auto gemm = [&](const float* invv, int wl_i, const float* A2, int wr_i,
                    float* outp, int N, int acc) {
        int K = A2 ? 256 : 128;
        size_t smem = (size_t)(K * D + BM * K) * sizeof(float);
        k_gemm<<<(N + BM - 1) / BM, 128, smem>>>(
            AGG, invv, Wl + (size_t)wl_i * D * D, A2,
            A2 ? (Wr + (size_t)wr_i * D * D) : nullptr,
            bL + (size_t)wl_i * D, outp, N, acc);
    };
    auto bnrelu = [&](float* x, int N, int bn_i) {
        cudaMemsetAsync(bnsum, 0, D * sizeof(float), 0);
        cudaMemsetAsync(bnsq, 0, D * sizeof(float), 0);
        k_bnstats<<<1024, D>>>(x, N);
        k_bnapply<<<(N * D + 255) / 256, 256>>>(x, N, bng + (size_t)bn_i * D,
                                                bnb + (size_t)bn_i * D);
    };

    // ---- Layer 0 ----
    scatter(x_p, e_pp, Epp, np); gemm(inv[0], 0, x_p, 0, P0, np, 0);
    scatter(x_p, e_pa, Epa, na); gemm(inv[1], 1, x_a, 1, A0, na, 0);
    bnrelu(P0, np, 0);
    bnrelu(A0, na, 1);

    // ---- Layer 1 ----
    scatter(P0, e_pp, Epp, np); gemm(inv[0], 2, P0, 2, P1, np, 0);
    scatter(A0, e_ap, Eap, np); gemm(inv[2], 4, P0, 4, P1, np, 1);
    scatter(P0, e_pa, Epa, na); gemm(inv[1], 3, A0, 3, A1, na, 0);
    scatter(A0, e_ai, Eai, ni); gemm(inv[3], 5, nullptr, 5, I1, ni, 0);
    bnrelu(P1, np, 2);
    bnrelu(A1, na, 3);
    bnrelu(I1, ni, 4);

    // ---- Layer 2 (writes directly into d_out: [p2 | a2 | i2]) ----
    float* P2o = (float*)d_out;
    float* A2o = P2o + (size_t)np * D;
    float* I2o = A2o + (size_t)na * D;
    scatter(P1, e_pp, Epp, np); gemm(inv[0], 6,  P1, 6,  P2o, np, 0);
    scatter(A1, e_ap, Eap, np); gemm(inv[2], 8,  P1, 8,  P2o, np, 1);
    scatter(P1, e_pa, Epa, na); gemm(inv[1], 7,  A1, 7,  A2o, na, 0);
    scatter(I1, e_ia, Eia, na); gemm(inv[4], 10, A1, 10, A2o, na, 1);
    scatter(A1, e_ai, Eai, ni); gemm(inv[3], 9,  I1, 9,  I2o, ni, 0);
}

// round 3
// speedup vs baseline: 2.3687x; 2.3687x over previous
#include <cuda_runtime.h>
#include <cstddef>

#define D 128
#define NP 200000
#define NA 150000
#define NI 10000
#define BK 16
#define EPS 1e-5f

// ---------------- scratch (device globals; no allocation allowed) -------------
__device__ float g_P0[(size_t)NP * D];
__device__ float g_A0[(size_t)NA * D];
__device__ float g_P1[(size_t)NP * D];
__device__ float g_A1[(size_t)NA * D];
__device__ float g_I1[(size_t)NI * D];
__device__ float g_AGG[(size_t)NP * D];
__device__ float g_AGG2[(size_t)NP * D];
__device__ int   g_cnt[5][NP];
__device__ float g_inv[5][NP];
__device__ float g_bnsum[D];
__device__ float g_bnsq[D];

// ---------------- small kernels -----------------------------------------------

__global__ void k_count(const int* __restrict__ dst, int E, int* __restrict__ cnt) {
    int i = blockIdx.x * blockDim.x + threadIdx.x;
    if (i < E) atomicAdd(&cnt[dst[i]], 1);
}

__global__ void k_inv(const int* __restrict__ cnt, float* __restrict__ inv, int n) {
    int i = blockIdx.x * blockDim.x + threadIdx.x;
    if (i < n) inv[i] = 1.0f / (float)max(cnt[i], 1);
}

// One warp per edge; each lane moves one float4 (coalesced 512B read) and does
// a single vectorized red.global.add.v4.f32 (4x fewer L2 atomic ops vs scalar).
__global__ void k_scatter(const float* __restrict__ x, const int* __restrict__ src,
                          const int* __restrict__ dst, int E, float* __restrict__ agg) {
    int gid  = blockIdx.x * blockDim.x + threadIdx.x;
    int e    = gid >> 5;
    int lane = gid & 31;
    if (e >= E) return;
    int s = src[e], d = dst[e];
    float4 v = ((const float4*)(x + (size_t)s * D))[lane];
    float* a = agg + (size_t)d * D + lane * 4;
    asm volatile("red.global.add.v4.f32 [%0], {%1,%2,%3,%4};"
                 :: "l"(a), "f"(v.x), "f"(v.y), "f"(v.z), "f"(v.w) : "memory");
}

// ---------------- fused multi-source GEMM --------------------------------------
// out[N,128] = sum_{s<nsrc} (A_s * inv_s)[N,128] @ (W_s (+ W2_s))[128,128] + bias1 (+bias2)
// 128x128 output tile per block, BK=16 double-buffered, 256 threads, 8x8 microtile.
__global__ void __launch_bounds__(256)
k_gemm(const float* __restrict__ A0, const float* __restrict__ i0p,
       const float* __restrict__ W0a, const float* __restrict__ W0b,
       const float* __restrict__ A1, const float* __restrict__ i1p,
       const float* __restrict__ W1a, const float* __restrict__ W1b,
       const float* __restrict__ A2, const float* __restrict__ i2p,
       const float* __restrict__ W2a, const float* __restrict__ W2b,
       const float* __restrict__ b1p, const float* __restrict__ b2p,
       float* __restrict__ out, int N, int nsrc) {
    __shared__ float sA[2][BK][132];   // transposed A tile, padded
    __shared__ float sB[2][BK][128];   // W tile

    int tid  = threadIdx.x;
    int base = blockIdx.x * 128;
    int tx   = tid & 15;    // 16 col groups * 8 = 128 cols
    int ty   = tid >> 4;    // 16 row groups * 8 = 128 rows

    // A loader mapping: 2 float4 per thread, pair-of-threads per row
    int lrow    = tid >> 1;        // 0..127
    int lc4base = (tid & 1) * 2;   // float4 index 0/2 within the 16-col chunk
    int k0      = lc4base * 4;

    auto loadA = [&](int kc, int buf) {
        int s   = kc >> 3;
        int off = (kc & 7) * BK;
        const float *A, *iv;
        if (s == 0)      { A = A0; iv = i0p; }
        else if (s == 1) { A = A1; iv = i1p; }
        else             { A = A2; iv = i2p; }
        int row = base + lrow;
        float4 v0 = make_float4(0.f, 0.f, 0.f, 0.f), v1 = v0;
        if (row < N) {
            const float* ap = A + (size_t)row * D + off;
            v0 = ((const float4*)ap)[lc4base];
            v1 = ((const float4*)ap)[lc4base + 1];
            if (iv) {
                float sc = iv[row];
                v0.x *= sc; v0.y *= sc; v0.z *= sc; v0.w *= sc;
                v1.x *= sc; v1.y *= sc; v1.z *= sc; v1.w *= sc;
            }
        }
        sA[buf][k0 + 0][lrow] = v0.x; sA[buf][k0 + 1][lrow] = v0.y;
        sA[buf][k0 + 2][lrow] = v0.z; sA[buf][k0 + 3][lrow] = v0.w;
        sA[buf][k0 + 4][lrow] = v1.x; sA[buf][k0 + 5][lrow] = v1.y;
        sA[buf][k0 + 6][lrow] = v1.z; sA[buf][k0 + 7][lrow] = v1.w;
    };

    auto loadB = [&](int kc, int buf) {
        int s   = kc >> 3;
        int off = (kc & 7) * BK;
        const float *wa, *wb;
        if (s == 0)      { wa = W0a; wb = W0b; }
        else if (s == 1) { wa = W1a; wb = W1b; }
        else             { wa = W2a; wb = W2b; }
#pragma unroll
        for (int q = 0; q < 2; q++) {
            int idx = tid * 2 + q;
            int r   = idx >> 5;
            int c4  = idx & 31;
            float4 v = ((const float4*)(wa + (size_t)(off + r) * D))[c4];
            if (wb) {
                float4 u = ((const float4*)(wb + (size_t)(off + r) * D))[c4];
                v.x += u.x; v.y += u.y; v.z += u.z; v.w += u.w;
            }
            ((float4*)&sB[buf][r][0])[c4] = v;
        }
    };

    float acc[8][8];
#pragma unroll
    for (int i = 0; i < 8; i++)
#pragma unroll
        for (int j = 0; j < 8; j++) acc[i][j] = 0.f;

    int nk = nsrc * 8;
    loadA(0, 0); loadB(0, 0);
    __syncthreads();

    for (int kc = 0; kc < nk; kc++) {
        int buf = kc & 1;
        if (kc + 1 < nk) { loadA(kc + 1, buf ^ 1); loadB(kc + 1, buf ^ 1); }
#pragma unroll
        for (int kk = 0; kk < BK; kk++) {
            float4 a0 = *(const float4*)&sA[buf][kk][ty * 8];
            float4 a1 = *(const float4*)&sA[buf][kk][ty * 8 + 4];
            float4 b0 = *(const float4*)&sB[buf][kk][tx * 8];
            float4 b1 = *(const float4*)&sB[buf][kk][tx * 8 + 4];
            float a[8] = {a0.x, a0.y, a0.z, a0.w, a1.x, a1.y, a1.z, a1.w};
            float b[8] = {b0.x, b0.y, b0.z, b0.w, b1.x, b1.y, b1.z, b1.w};
#pragma unroll
            for (int i = 0; i < 8; i++)
#pragma unroll
                for (int j = 0; j < 8; j++) acc[i][j] = fmaf(a[i], b[j], acc[i][j]);
        }
        __syncthreads();
    }

    float bb[8];
#pragma unroll
    for (int j = 0; j < 8; j++) {
        bb[j] = b1p[tx * 8 + j];
        if (b2p) bb[j] += b2p[tx * 8 + j];
    }
#pragma unroll
    for (int i = 0; i < 8; i++) {
        int row = base + ty * 8 + i;
        if (row >= N) continue;
        float4 o0 = make_float4(acc[i][0] + bb[0], acc[i][1] + bb[1],
                                acc[i][2] + bb[2], acc[i][3] + bb[3]);
        float4 o1 = make_float4(acc[i][4] + bb[4], acc[i][5] + bb[5],
                                acc[i][6] + bb[6], acc[i][7] + bb[7]);
        float4* op = (float4*)(out + (size_t)row * D + tx * 8);
        op[0] = o0; op[1] = o1;
    }
}

// ---------------- BN over relu ------------------------------------------------

__global__ void k_bnstats(const float* __restrict__ x, int N) {
    int c = threadIdx.x;  // 128 threads
    float s = 0.f, sq = 0.f;
    for (int r = blockIdx.x; r < N; r += gridDim.x) {
        float v = fmaxf(x[(size_t)r * D + c], 0.f);
        s += v; sq += v * v;
    }
    atomicAdd(&g_bnsum[c], s);
    atomicAdd(&g_bnsq[c], sq);
}

__global__ void k_bnapply(float* __restrict__ x, int N,
                          const float* __restrict__ g, const float* __restrict__ b) {
    int idx = blockIdx.x * blockDim.x + threadIdx.x;
    if (idx >= N * D) return;
    int c = idx & (D - 1);
    float m   = g_bnsum[c] / (float)N;
    float var = g_bnsq[c] / (float)N - m * m;
    float v = fmaxf(x[idx], 0.f);
    x[idx] = (v - m) * rsqrtf(var + EPS) * g[c] + b[c];
}

// ---------------- host orchestration -------------------------------------------

extern "C" void kernel_launch(void* const* d_in, const int* in_sizes, int n_in,
                              void* d_out, int out_size) {
    const float* x_p = (const float*)d_in[0];
    const float* x_a = (const float*)d_in[1];
    const int* e_pp = (const int*)d_in[3];
    const int* e_pa = (const int*)d_in[4];
    const int* e_ap = (const int*)d_in[5];
    const int* e_ai = (const int*)d_in[6];
    const int* e_ia = (const int*)d_in[7];
    const float* Wl  = (const float*)d_in[8];
    const float* bL  = (const float*)d_in[9];
    const float* Wr  = (const float*)d_in[10];
    const float* bng = (const float*)d_in[11];
    const float* bnb = (const float*)d_in[12];

    const int np = in_sizes[0] / D;
    const int na = in_sizes[1] / D;
    const int ni = in_sizes[2] / D;
    const int Epp = in_sizes[3] / 2, Epa = in_sizes[4] / 2, Eap = in_sizes[5] / 2;
    const int Eai = in_sizes[6] / 2, Eia = in_sizes[7] / 2;

    float *P0, *A0, *P1, *A1, *I1, *AGG, *AGG2, *bnsum, *bnsq;
    int   (*cnt)[NP];
    float (*inv)[NP];
    cudaGetSymbolAddress((void**)&P0,   g_P0);
    cudaGetSymbolAddress((void**)&A0,   g_A0);
    cudaGetSymbolAddress((void**)&P1,   g_P1);
    cudaGetSymbolAddress((void**)&A1,   g_A1);
    cudaGetSymbolAddress((void**)&I1,   g_I1);
    cudaGetSymbolAddress((void**)&AGG,  g_AGG);
    cudaGetSymbolAddress((void**)&AGG2, g_AGG2);
    cudaGetSymbolAddress((void**)&cnt,  g_cnt);
    cudaGetSymbolAddress((void**)&inv,  g_inv);
    cudaGetSymbolAddress((void**)&bnsum, g_bnsum);
    cudaGetSymbolAddress((void**)&bnsq,  g_bnsq);

    const float* WL[11]; const float* WR[11]; const float* BL[11];
    for (int i = 0; i < 11; i++) {
        WL[i] = Wl + (size_t)i * D * D;
        WR[i] = Wr + (size_t)i * D * D;
        BL[i] = bL + (size_t)i * D;
    }

    // ---- per-edge-type in-degree reciprocals (recomputed each call) ----
    struct { const int* e; int E; int ndst; } cl[5] = {
        {e_pp, Epp, np}, {e_pa, Epa, na}, {e_ap, Eap, np}, {e_ai, Eai, ni}, {e_ia, Eia, na}};
    for (int t = 0; t < 5; t++) {
        cudaMemsetAsync(cnt[t], 0, (size_t)cl[t].ndst * sizeof(int), 0);
        k_count<<<(cl[t].E + 255) / 256, 256>>>(cl[t].e + cl[t].E, cl[t].E, cnt[t]);
        k_inv<<<(cl[t].ndst + 255) / 256, 256>>>(cnt[t], inv[t], cl[t].ndst);
    }

    auto scatter = [&](const float* x, const int* e, int E, int ndst, float* aggbuf) {
        cudaMemsetAsync(aggbuf, 0, (size_t)ndst * D * sizeof(float), 0);
        long long thr = (long long)E * 32;
        k_scatter<<<(unsigned)((thr + 255) / 256), 256>>>(x, e, e + E, E, aggbuf);
    };

    // gemm with up to 3 sources
    auto gemm = [&](float* outp, int N,
                    const float* a0, const float* i0, const float* w0a, const float* w0b,
                    const float* a1, const float* i1, const float* w1a, const float* w1b,
                    const float* a2, const float* i2, const float* w2a, const float* w2b,
                    const float* bias1, const float* bias2, int nsrc) {
        k_gemm<<<(N + 127) / 128, 256>>>(a0, i0, w0a, w0b, a1, i1, w1a, w1b,
                                         a2, i2, w2a, w2b, bias1, bias2, outp, N, nsrc);
    };
    auto bnrelu = [&](float* x, int N, int bn_i) {
        cudaMemsetAsync(bnsum, 0, D * sizeof(float), 0);
        cudaMemsetAsync(bnsq, 0, D * sizeof(float), 0);
        k_bnstats<<<1024, D>>>(x, N);
        k_bnapply<<<(N * D + 255) / 256, 256>>>(x, N, bng + (size_t)bn_i * D,
                                                bnb + (size_t)bn_i * D);
    };

    // ---- Layer 0 ----
    scatter(x_p, e_pp, Epp, np, AGG);
    gemm(P0, np, AGG, inv[0], WL[0], nullptr, x_p, nullptr, WR[0], nullptr,
         nullptr, nullptr, nullptr, nullptr, BL[0], nullptr, 2);
    scatter(x_p, e_pa, Epa, na, AGG);
    gemm(A0, na, AGG, inv[1], WL[1], nullptr, x_a, nullptr, WR[1], nullptr,
         nullptr, nullptr, nullptr, nullptr, BL[1], nullptr, 2);
    bnrelu(P0, np, 0);
    bnrelu(A0, na, 1);

    // ---- Layer 1 ----
    scatter(P0, e_pp, Epp, np, AGG);
    scatter(A0, e_ap, Eap, np, AGG2);
    gemm(P1, np, AGG, inv[0], WL[2], nullptr, AGG2, inv[2], WL[4], nullptr,
         P0, nullptr, WR[2], WR[4], BL[2], BL[4], 3);
    scatter(P0, e_pa, Epa, na, AGG);
    gemm(A1, na, AGG, inv[1], WL[3], nullptr, A0, nullptr, WR[3], nullptr,
         nullptr, nullptr, nullptr, nullptr, BL[3], nullptr, 2);
    scatter(A0, e_ai, Eai, ni, AGG);
    gemm(I1, ni, AGG, inv[3], WL[5], nullptr, nullptr, nullptr, nullptr, nullptr,
         nullptr, nullptr, nullptr, nullptr, BL[5], nullptr, 1);
    bnrelu(P1, np, 2);
    bnrelu(A1, na, 3);
    bnrelu(I1, ni, 4);

    // ---- Layer 2 (writes directly into d_out: [p2 | a2 | i2]) ----
    float* P2o = (float*)d_out;
    float* A2o = P2o + (size_t)np * D;
    float* I2o = A2o + (size_t)na * D;
    scatter(P1, e_pp, Epp, np, AGG);
    scatter(A1, e_ap, Eap, np, AGG2);
    gemm(P2o, np, AGG, inv[0], WL[6], nullptr, AGG2, inv[2], WL[8], nullptr,
         P1, nullptr, WR[6], WR[8], BL[6], BL[8], 3);
    scatter(P1, e_pa, Epa, na, AGG);
    scatter(I1, e_ia, Eia, na, AGG2);
    gemm(A2o, na, AGG, inv[1], WL[7], nullptr, AGG2, inv[4], WL[10], nullptr,
         A1, nullptr, WR[7], WR[10], BL[7], BL[10], 3);
    scatter(A1, e_ai, Eai, ni, AGG);
    gemm(I2o, ni, AGG, inv[3], WL[9], nullptr, I1, nullptr, WR[9], nullptr,
         nullptr, nullptr, nullptr, nullptr, BL[9], nullptr, 2);
}